// round 17
// baseline (speedup 1.0000x reference)
#include <cuda_runtime.h>
#include <cuda_fp16.h>
#include <cstdint>

// TALayer = 9-tap conv, tap offsets d_j = 16*(j/3)+(j%3)-17.
// GEMM: D[o,t] = sum_k W[o,k]*X[k,t], k=(j,c), K=576.
// fp16 m16n8k16. Two-kernel: prep (x->fp16 t-major g_xt + W frags),
// then persistent mma kernel: 384 thr (12 warps), warp tile 32o x 64t,
// T_TILE=384, double-buffered cp.async fp16 staging. Crossbar bytes/MAC
// reduced 28% vs 32o x 32t (W frag reuse doubled).

#define T_LEN   65536
#define TP      65728        // 32 front pad + 65536 + 160 back pad
#define NB      8
#define NO      64
#define NC      64
#define T_TILE  384
#define HALO    17
#define XROWS   418          // T_TILE + 2*HALO
#define XPW     36           // words per smem x row (144B; LDS.32 bank-clean)
#define NCHUNK  36           // K=576/16
#define GRID    148
#define TPB     171          // tiles per batch (last covers 256 t)
#define NTILES  (NB*TPB)     // 1368

// smem byte offsets
#define WFOFF   0
#define WFBYTES (NCHUNK*4*32*16)     // 73728
#define XS0     WFBYTES
#define XBUFB   (XROWS*XPW*4)        // 60192
#define SMTOT   (XS0 + 2*XBUFB)      // 194112

__device__ uint32_t g_wfrag[NCHUNK*4*32*4];
// x fp16, [b][t+32][c], rows of 128B, pads zeroed.
__device__ __align__(16) __half g_xt[(size_t)NB * TP * NC];

__device__ __forceinline__ uint32_t packh2(float lo, float hi) {
    __half2 h = __floats2half2_rn(lo, hi);
    return *(uint32_t*)&h;
}

// Fused prep: transpose+convert x; first 18 blocks also cook W fragments.
__global__ void prep_all(const float* __restrict__ x, const float* __restrict__ w) {
    int tid = threadIdx.x;

    if (blockIdx.x < 18) {
        int i = blockIdx.x * 256 + tid;
        if (i < NCHUNK * 128) {
            int q = i >> 7, rr = i & 127, mt = rr >> 5, lane = rr & 31;
            int j = q >> 2, cq = q & 3;
            int o0 = mt * 16 + (lane >> 2);
            int c0 = cq * 16 + (lane & 3) * 2;
            uint4 u;
            u.x = packh2(w[o0*576 + c0*9 + j],        w[o0*576 + (c0+1)*9 + j]);
            u.y = packh2(w[(o0+8)*576 + c0*9 + j],    w[(o0+8)*576 + (c0+1)*9 + j]);
            u.z = packh2(w[o0*576 + (c0+8)*9 + j],    w[o0*576 + (c0+9)*9 + j]);
            u.w = packh2(w[(o0+8)*576 + (c0+8)*9 + j],w[(o0+8)*576 + (c0+9)*9 + j]);
            ((uint4*)g_wfrag)[q * 128 + mt * 32 + lane] = u;
        }
    }

    __shared__ __half tile[256][66];
    int b  = blockIdx.x >> 8;
    int tt = blockIdx.x & 255;
    int t0 = tt << 8;
    uint32_t* dst = (uint32_t*)g_xt;

    if (tt == 0) {          // zero front pad rows [0,32)
        for (int i = tid; i < 32 * 32; i += 256)
            dst[((size_t)b*TP + (i >> 5))*32 + (i & 31)] = 0;
    } else if (tt == 255) { // zero back pad rows [TP-160, TP)
        for (int i = tid; i < 160 * 32; i += 256)
            dst[((size_t)b*TP + TP - 160 + (i >> 5))*32 + (i & 31)] = 0;
    }

#pragma unroll 8
    for (int c = 0; c < 64; ++c)
        tile[tid][c] = __float2half_rn(x[((size_t)(b*64 + c))*T_LEN + t0 + tid]);
    __syncthreads();
#pragma unroll 8
    for (int it = 0; it < 32; ++it) {
        int idx = it * 256 + tid;
        int i = idx >> 5, wd = idx & 31;
        __half2 h2;
        h2.x = tile[i][2*wd]; h2.y = tile[i][2*wd + 1];
        dst[((size_t)b*TP + 32 + t0 + i)*32 + wd] = *(uint32_t*)&h2;
    }
}

extern __shared__ char sm[];

__device__ __forceinline__ uint32_t s2u(const void* p) {
    uint32_t a;
    asm("{ .reg .u64 t; cvta.to.shared.u64 t, %1; cvt.u32.u64 %0, t; }"
        : "=r"(a) : "l"(p));
    return a;
}

#define CP_ASYNC16(d, s) \
    asm volatile("cp.async.cg.shared.global [%0], [%1], 16;" :: "r"(d), "l"(s))
#define CP_COMMIT() asm volatile("cp.async.commit_group;" ::: "memory")
#define CP_WAIT0()  asm volatile("cp.async.wait_group 0;" ::: "memory")

// Stage one 384-t tile's fp16 rows (418 x 128B) into a smem buffer.
__device__ __forceinline__ void stage_x(int b, int t0, uint32_t dstu, int tid) {
    const char* src = (const char*)(g_xt + ((size_t)b*TP + 15 + t0) * 64);
#pragma unroll
    for (int s = 0; s < 9; ++s) {
        int idx = s * 384 + tid;
        if (idx < XROWS * 8) {
            int r = idx >> 3, ch = idx & 7;
            CP_ASYNC16(dstu + r*(XPW*4) + ch*16, src + (size_t)r*128 + ch*16);
        }
    }
}

__global__ __launch_bounds__(384, 1) void taconv_mma(
    const float* __restrict__ bias, float* __restrict__ out)
{
    const int tid  = threadIdx.x;
    const int wid  = tid >> 5;
    const int lane = tid & 31;
    const int og   = wid & 1;        // o-half: 2 mtiles of 16
    const int tg   = wid >> 1;       // t-group: 64 t each (6 groups)

    {
        const uint4* gw = (const uint4*)g_wfrag;
        uint4* sw = (uint4*)(sm + WFOFF);
        for (int i = tid; i < NCHUNK * 128; i += 384) sw[i] = gw[i];
    }
    const int oA0 = og * 32 + (lane >> 2);
    float bv[2][2];
#pragma unroll
    for (int m = 0; m < 2; ++m) {
        bv[m][0] = __ldg(bias + oA0 + m * 16);
        bv[m][1] = __ldg(bias + oA0 + m * 16 + 8);
    }

    const uint32_t smb = s2u(sm);
    const int wrow = tg * 64 + (lane >> 2);   // B-frag t-row base (pre-shift)

    int tile = blockIdx.x;
    {
        int b = tile / TPB, t0 = (tile - b * TPB) * T_TILE;
        stage_x(b, t0, smb + XS0, tid);
    }
    CP_COMMIT();

    int cur = 0;
    for (; tile < NTILES; tile += GRID) {
        const int b  = tile / TPB;
        const int t0 = (tile - b * TPB) * T_TILE;

        CP_WAIT0();
        __syncthreads();      // buffer cur staged; prev compute done

        // prefetch next tile into the other buffer (overlaps compute)
        if (tile + GRID < NTILES) {
            int tn = tile + GRID;
            int bn = tn / TPB, t0n = (tn - bn * TPB) * T_TILE;
            stage_x(bn, t0n, smb + XS0 + (cur ^ 1) * XBUFB, tid);
        }
        CP_COMMIT();

        const uint32_t* xs = (const uint32_t*)(sm + XS0 + cur * XBUFB);
        const uint4* wf_base = (const uint4*)(sm + WFOFF);

        // acc pre-loaded with bias: [m][nt][4]
        float acc[2][8][4];
#pragma unroll
        for (int m = 0; m < 2; ++m)
#pragma unroll
            for (int n = 0; n < 8; ++n) {
                acc[m][n][0] = bv[m][0]; acc[m][n][1] = bv[m][0];
                acc[m][n][2] = bv[m][1]; acc[m][n][3] = bv[m][1];
            }

#pragma unroll
        for (int j = 0; j < 9; ++j) {
            const int offj = 16 * (j / 3) + (j % 3);   // d_j + HALO
#pragma unroll
            for (int cq = 0; cq < 4; ++cq) {
                const int q = j * 4 + cq;
                uint4 wf[2];
#pragma unroll
                for (int m = 0; m < 2; ++m)
                    wf[m] = wf_base[(q * 4 + og * 2 + m) * 32 + lane];

                uint32_t bb[8][2];
                const uint32_t* bp =
                    xs + (wrow + offj) * XPW + cq * 8 + (lane & 3);
#pragma unroll
                for (int nt = 0; nt < 8; ++nt) {
                    bb[nt][0] = bp[nt * 8 * XPW];
                    bb[nt][1] = bp[nt * 8 * XPW + 4];
                }
#pragma unroll
                for (int m = 0; m < 2; ++m)
#pragma unroll
                    for (int nt = 0; nt < 8; ++nt)
                        asm volatile(
                            "mma.sync.aligned.m16n8k16.row.col.f32.f16.f16.f32 "
                            "{%0,%1,%2,%3}, {%4,%5,%6,%7}, {%8,%9}, {%0,%1,%2,%3};"
                            : "+f"(acc[m][nt][0]), "+f"(acc[m][nt][1]),
                              "+f"(acc[m][nt][2]), "+f"(acc[m][nt][3])
                            : "r"(wf[m].x), "r"(wf[m].y),
                              "r"(wf[m].z), "r"(wf[m].w),
                              "r"(bb[nt][0]), "r"(bb[nt][1]));
            }
        }

        // ---- epilogue: pure stores (bias in acc); mask t >= T_LEN ----
        if (t0 + tg * 64 < T_LEN) {
            float* ob = out + (size_t)b * NO * T_LEN + t0 + tg * 64
                            + 2 * (lane & 3);
#pragma unroll
            for (int m = 0; m < 2; ++m) {
                int oA = oA0 + m * 16;
#pragma unroll
                for (int nt = 0; nt < 8; ++nt) {
                    *(float2*)(ob + (size_t)oA * T_LEN + nt * 8) =
                        make_float2(acc[m][nt][0], acc[m][nt][1]);
                    *(float2*)(ob + (size_t)(oA + 8) * T_LEN + nt * 8) =
                        make_float2(acc[m][nt][2], acc[m][nt][3]);
                }
            }
        }
        cur ^= 1;
    }
}

extern "C" void kernel_launch(void* const* d_in, const int* in_sizes, int n_in,
                              void* d_out, int out_size) {
    const float* x    = (const float*)d_in[0];
    const float* w    = (const float*)d_in[1];
    const float* bias = (const float*)d_in[2];
    float* out = (float*)d_out;

    prep_all<<<NB * 256, 256>>>(x, w);

    cudaFuncSetAttribute(taconv_mma,
                         cudaFuncAttributeMaxDynamicSharedMemorySize, SMTOT);
    taconv_mma<<<GRID, 384, SMTOT>>>(bias, out);
}